// round 10
// baseline (speedup 1.0000x reference)
#include <cuda_runtime.h>
#include <cuda_bf16.h>
#include <cstdint>

#define NB 64
#define NN 512
#define ND 128

// pre-normalized features, bf16 hi/lo planes
__device__ uint4 g_hi[(NB * NN * ND * 2) / 16];
__device__ uint4 g_lo[(NB * NN * ND * 2) / 16];

__device__ __forceinline__ uint32_t smem_u32(const void* p) {
    uint32_t a;
    asm("{ .reg .u64 t; cvta.to.shared.u64 t, %1; cvt.u32.u64 %0, t; }" : "=r"(a) : "l"(p));
    return a;
}
__device__ __forceinline__ float fsqrt_approx(float x) {
    float r;
    asm("sqrt.approx.f32 %0, %1;" : "=f"(r) : "f"(x));
    return r;
}

#define LDSM_X4(r, addr)                                                                  \
    asm volatile("ldmatrix.sync.aligned.m8n8.x4.shared.b16 {%0,%1,%2,%3}, [%4];"          \
                 : "=r"((r)[0]), "=r"((r)[1]), "=r"((r)[2]), "=r"((r)[3]) : "r"(addr))

#define CP_ASYNC16(sa, gp)                                                                \
    asm volatile("cp.async.cg.shared.global [%0], [%1], 16;" :: "r"(sa), "l"(gp) : "memory")
#define CP_COMMIT() asm volatile("cp.async.commit_group;" ::: "memory")
#define CP_WAIT(n)  asm volatile("cp.async.wait_group %0;" :: "n"(n) : "memory")

__device__ __forceinline__ void mma16816(float* c, uint32_t a0, uint32_t a1, uint32_t a2,
                                         uint32_t a3, uint32_t b0, uint32_t b1) {
    asm volatile("mma.sync.aligned.m16n8k16.row.col.f32.bf16.bf16.f32 "
                 "{%0,%1,%2,%3}, {%4,%5,%6,%7}, {%8,%9}, {%0,%1,%2,%3};"
                 : "+f"(c[0]), "+f"(c[1]), "+f"(c[2]), "+f"(c[3])
                 : "r"(a0), "r"(a1), "r"(a2), "r"(a3), "r"(b0), "r"(b1));
}

// smem: 128x128 tile-pair, K-chunk 32, double-buffered. Row stride 80 B
// (r*80 mod 128B cycles all 8 16B-banks -> conflict-free ldmatrix).
// Chunk planes: Ahi, Alo, Bhi, Blo; 128 rows x 32 bf16 each.
#define SMA32 80
#define PLANE 10240           // 128*80
#define CHUNK 40960           // 4 planes
#define OFF_CI 81920          // 128 float2
#define OFF_CJ 82944
#define SMEM_TOTAL 83968
#define OFF_AVT 0             // 128*132*4 = 67584, reuses buffers after MMA
#define AVT_S 132

// ---------- prep: normalize rows, split to bf16 hi/lo ----------
__global__ void prep_kernel(const float* __restrict__ fea) {
    int row  = blockIdx.x * 8 + (threadIdx.x >> 5);
    int lane = threadIdx.x & 31;
    float4 v = reinterpret_cast<const float4*>(fea + (size_t)row * ND)[lane];
    float s = v.x * v.x + v.y * v.y + v.z * v.z + v.w * v.w;
    #pragma unroll
    for (int o = 16; o > 0; o >>= 1) s += __shfl_xor_sync(0xffffffffu, s, o);
    float rn = 1.0f / fmaxf(sqrtf(s), 1e-8f);
    float x0 = v.x * rn, x1 = v.y * rn, x2 = v.z * rn, x3 = v.w * rn;
    __nv_bfloat16 h0 = __float2bfloat16(x0), h1 = __float2bfloat16(x1);
    __nv_bfloat16 h2 = __float2bfloat16(x2), h3 = __float2bfloat16(x3);
    __nv_bfloat16 l0 = __float2bfloat16(x0 - __bfloat162float(h0));
    __nv_bfloat16 l1 = __float2bfloat16(x1 - __bfloat162float(h1));
    __nv_bfloat16 l2 = __float2bfloat16(x2 - __bfloat162float(h2));
    __nv_bfloat16 l3 = __float2bfloat16(x3 - __bfloat162float(h3));
    uint2 hv, lv;
    hv.x = (uint32_t)__bfloat16_as_ushort(h0) | ((uint32_t)__bfloat16_as_ushort(h1) << 16);
    hv.y = (uint32_t)__bfloat16_as_ushort(h2) | ((uint32_t)__bfloat16_as_ushort(h3) << 16);
    lv.x = (uint32_t)__bfloat16_as_ushort(l0) | ((uint32_t)__bfloat16_as_ushort(l1) << 16);
    lv.y = (uint32_t)__bfloat16_as_ushort(l2) | ((uint32_t)__bfloat16_as_ushort(l3) << 16);
    reinterpret_cast<uint2*>(g_hi)[(size_t)row * 32 + lane] = hv;
    reinterpret_cast<uint2*>(g_lo)[(size_t)row * 32 + lane] = lv;
}

// issue one K32 chunk: 4 planes x 128 rows x 32 bf16 = 2048 uint4 = 8/thread
__device__ __forceinline__ void issue_chunk(uint32_t bufBase, int tid, int b,
                                            int iBase, int jBase, int kc) {
    #pragma unroll
    for (int it = 0; it < 8; it++) {
        int idx = tid + it * 256;
        int plane = idx >> 9;              // 0 Ahi, 1 Alo, 2 Bhi, 3 Blo
        int e = idx & 511;
        int row = e >> 2;
        int c8 = (e & 3) * 8;
        int grow = ((plane < 2) ? iBase : jBase) + row;
        const uint4* src = (plane & 1) ? g_lo : g_hi;
        const uint4* gp = &src[((size_t)(b * NN + grow) * ND + kc * 32 + c8) >> 3];
        uint32_t sa = bufBase + (uint32_t)(plane * PLANE + row * SMA32 + c8 * 2);
        CP_ASYNC16(sa, gp);
    }
    CP_COMMIT();
}

// ---------- main: 128x128 tile-pairs, 256 threads, 2 CTAs/SM ----------
__global__ __launch_bounds__(256, 2)
void adj_mma_kernel(const float* __restrict__ coord, float* __restrict__ out) {
    extern __shared__ char sm[];
    const uint32_t smb = smem_u32(sm);
    const int tid  = threadIdx.x;
    const int wid  = tid >> 5;
    const int lane = tid & 31;
    const int wy = wid >> 2;          // 0..1, m dim (64 rows each)
    const int wx = wid & 3;           // 0..3, n dim (32 cols each)

    const int blk = blockIdx.x;
    const int b = blk / 10;
    const int t = blk % 10;
    const unsigned char bi_t[10] = {0,0,0,0,1,1,1,2,2,3};
    const unsigned char bj_t[10] = {0,1,2,3,1,2,3,2,3,3};
    const int iBase = bi_t[t] * 128;
    const int jBase = bj_t[t] * 128;
    const bool diag = (iBase == jBase);

    // prologue: chunks 0,1 in flight
    issue_chunk(smb,         tid, b, iBase, jBase, 0);
    issue_chunk(smb + CHUNK, tid, b, iBase, jBase, 1);

    // stage coords while loads stream
    {
        float2* ci2 = reinterpret_cast<float2*>(sm + OFF_CI);
        float2* cj2 = reinterpret_cast<float2*>(sm + OFF_CJ);
        if (tid < 128)
            ci2[tid] = reinterpret_cast<const float2*>(coord)[(size_t)b * NN + iBase + tid];
        else
            cj2[tid - 128] = reinterpret_cast<const float2*>(coord)[(size_t)b * NN + jBase + (tid - 128)];
    }

    float acc[4][4][4];               // [mt][nt][quad]
    #pragma unroll
    for (int mt = 0; mt < 4; mt++)
        #pragma unroll
        for (int nt = 0; nt < 4; nt++)
            #pragma unroll
            for (int q = 0; q < 4; q++) acc[mt][nt][q] = 0.0f;

    const uint32_t aOff = (uint32_t)((wy * 64 + lane) * SMA32);     // s=0 slice
    const uint32_t bOff = (uint32_t)(2 * PLANE + (wx * 32 + lane) * SMA32);

    #pragma unroll
    for (int kc = 0; kc < 4; kc++) {
        if (kc < 3) CP_WAIT(1); else CP_WAIT(0);
        __syncthreads();

        const uint32_t buf = smb + (uint32_t)((kc & 1) * CHUNK);
        const uint32_t aH0 = buf + aOff;              // rows wy*64..+31
        const uint32_t aH1 = aH0 + 32 * SMA32;        // rows wy*64+32..+63
        const uint32_t bH  = buf + bOff;
        const uint32_t bL  = bH + PLANE;

        #pragma unroll
        for (int ks = 0; ks < 2; ks++) {
            const uint32_t co = (uint32_t)(ks * 32);
            // A-hi fragments for all 4 mt (two 32-row slices)
            uint32_t a0h1[4], a0h2[4], a1h1[4], a1h2[4], bh1[4], bh2[4];
            LDSM_X4(a0h1, aH0 + co);
            LDSM_X4(a0h2, aH0 + co + 16);
            LDSM_X4(a1h1, aH1 + co);
            LDSM_X4(a1h2, aH1 + co + 16);
            LDSM_X4(bh1, bH + co);
            LDSM_X4(bh2, bH + co + 16);
            // hi*hi
            #pragma unroll
            for (int u = 0; u < 2; u++)
                #pragma unroll
                for (int nt = 0; nt < 4; nt++) {
                    mma16816(acc[u][nt],     a0h1[u*2], a0h1[u*2+1], a0h2[u*2], a0h2[u*2+1],
                             bh1[nt], bh2[nt]);
                    mma16816(acc[2 + u][nt], a1h1[u*2], a1h1[u*2+1], a1h2[u*2], a1h2[u*2+1],
                             bh1[nt], bh2[nt]);
                }
            // hi*lo(B)
            {
                uint32_t bl1[4], bl2[4];
                LDSM_X4(bl1, bL + co);
                LDSM_X4(bl2, bL + co + 16);
                #pragma unroll
                for (int u = 0; u < 2; u++)
                    #pragma unroll
                    for (int nt = 0; nt < 4; nt++) {
                        mma16816(acc[u][nt],     a0h1[u*2], a0h1[u*2+1], a0h2[u*2], a0h2[u*2+1],
                                 bl1[nt], bl2[nt]);
                        mma16816(acc[2 + u][nt], a1h1[u*2], a1h1[u*2+1], a1h2[u*2], a1h2[u*2+1],
                                 bl1[nt], bl2[nt]);
                    }
            }
            // lo(A)*hi, slice by slice to cap live registers
            #pragma unroll
            for (int s = 0; s < 2; s++) {
                uint32_t al1[4], al2[4];
                const uint32_t aL = (s ? aH1 : aH0) + PLANE;   // lo plane, same slice
                LDSM_X4(al1, aL + co);
                LDSM_X4(al2, aL + co + 16);
                #pragma unroll
                for (int u = 0; u < 2; u++)
                    #pragma unroll
                    for (int nt = 0; nt < 4; nt++)
                        mma16816(acc[s*2 + u][nt], al1[u*2], al1[u*2+1], al2[u*2], al2[u*2+1],
                                 bh1[nt], bh2[nt]);
            }
        }

        __syncthreads();
        if (kc < 2) issue_chunk(buf, tid, b, iBase, jBase, kc + 2);
    }

    // epilogue: direct stores from fragments + transposed staging for mirror
    {
        const float2* ci2 = reinterpret_cast<const float2*>(sm + OFF_CI);
        const float2* cj2 = reinterpret_cast<const float2*>(sm + OFF_CJ);
        float* avt = reinterpret_cast<float*>(sm + OFF_AVT);
        float* outA = out;
        float* outS = out + (size_t)NB * NN * NN;
        const size_t base = (size_t)b * NN * NN;
        const int g = lane >> 2, q = lane & 3;

        #pragma unroll
        for (int mt = 0; mt < 4; mt++) {
            #pragma unroll
            for (int nt = 0; nt < 4; nt++) {
                const float* c = acc[mt][nt];
                const int lj = wx * 32 + nt * 8 + q * 2;       // 0..127
                const float2 cj0 = cj2[lj], cj1 = cj2[lj + 1];
                #pragma unroll
                for (int h = 0; h < 2; h++) {
                    const int li = wy * 64 + mt * 16 + g + h * 8;   // 0..127
                    const float2 ci = ci2[li];
                    float dx0 = ci.x - cj0.x, dy0 = ci.y - cj0.y;
                    float dx1 = ci.x - cj1.x, dy1 = ci.y - cj1.y;
                    float d20 = dx0 * dx0 + dy0 * dy0;
                    float d21 = dx1 * dx1 + dy1 * dy1;
                    bool s0 = diag && (li == lj);
                    bool s1 = diag && (li == lj + 1);
                    float av0 = s0 ? 0.0f : c[h * 2 + 0] * __expf(-fsqrt_approx(d20));
                    float av1 = s1 ? 0.0f : c[h * 2 + 1] * __expf(-fsqrt_approx(d21));
                    float sv0 = (!s0 && d20 < 1.0f) ? 1.0f : 0.0f;
                    float sv1 = (!s1 && d21 < 1.0f) ? 1.0f : 0.0f;
                    size_t ro = base + (size_t)(iBase + li) * NN + jBase + lj;
                    *reinterpret_cast<float2*>(outA + ro) = make_float2(av0, av1);
                    *reinterpret_cast<float2*>(outS + ro) = make_float2(sv0, sv1);
                    if (!diag) {
                        avt[(size_t)lj * AVT_S + li]       = av0;
                        avt[(size_t)(lj + 1) * AVT_S + li] = av1;
                    }
                }
            }
        }
    }

    // mirror pass: 128 rows (j) x 128 cols (i)
    if (!diag) {
        __syncthreads();
        const float* avt = reinterpret_cast<const float*>(sm + OFF_AVT);
        const float2* cj2 = reinterpret_cast<const float2*>(sm + OFF_CJ);
        const float4* ci4 = reinterpret_cast<const float4*>(sm + OFF_CI);
        float* outA = out;
        float* outS = out + (size_t)NB * NN * NN;
        const size_t base = (size_t)b * NN * NN;

        #pragma unroll
        for (int it = 0; it < 16; it++) {
            const int r = wid * 16 + it;     // local j row, 0..127
            float4 av4 = *reinterpret_cast<const float4*>(avt + (size_t)r * AVT_S + lane * 4);
            float2 cj = cj2[r];
            float4 p0 = ci4[lane * 2], p1 = ci4[lane * 2 + 1];
            float d0x = cj.x - p0.x, d0y = cj.y - p0.y;
            float d1x = cj.x - p0.z, d1y = cj.y - p0.w;
            float d2x = cj.x - p1.x, d2y = cj.y - p1.y;
            float d3x = cj.x - p1.z, d3y = cj.y - p1.w;
            float4 sv4;
            sv4.x = (d0x * d0x + d0y * d0y < 1.0f) ? 1.0f : 0.0f;
            sv4.y = (d1x * d1x + d1y * d1y < 1.0f) ? 1.0f : 0.0f;
            sv4.z = (d2x * d2x + d2y * d2y < 1.0f) ? 1.0f : 0.0f;
            sv4.w = (d3x * d3x + d3y * d3y < 1.0f) ? 1.0f : 0.0f;
            size_t ro = base + (size_t)(jBase + r) * NN + iBase + lane * 4;
            *reinterpret_cast<float4*>(outA + ro) = av4;
            *reinterpret_cast<float4*>(outS + ro) = sv4;
        }
    }
}

extern "C" void kernel_launch(void* const* d_in, const int* in_sizes, int n_in,
                              void* d_out, int out_size) {
    (void)in_sizes; (void)n_in; (void)out_size;
    const float* fea   = (const float*)d_in[0];
    const float* coord = (const float*)d_in[1];
    float* out = (float*)d_out;

    prep_kernel<<<NB * NN / 8, 256>>>(fea);

    cudaFuncSetAttribute(adj_mma_kernel, cudaFuncAttributeMaxDynamicSharedMemorySize, SMEM_TOTAL);
    adj_mma_kernel<<<NB * 10, 256, SMEM_TOTAL>>>(coord, out);
}

// round 11
// speedup vs baseline: 1.2490x; 1.2490x over previous
#include <cuda_runtime.h>
#include <cuda_fp16.h>
#include <cstdint>

#define NB 64
#define NN 512
#define ND 128

// pre-normalized features (scaled x16), fp16 hi/lo planes
__device__ uint4 g_hi[(NB * NN * ND * 2) / 16];
__device__ uint4 g_lo[(NB * NN * ND * 2) / 16];

__device__ __forceinline__ uint32_t smem_u32(const void* p) {
    uint32_t a;
    asm("{ .reg .u64 t; cvta.to.shared.u64 t, %1; cvt.u32.u64 %0, t; }" : "=r"(a) : "l"(p));
    return a;
}
__device__ __forceinline__ float fsqrt_approx(float x) {
    float r;
    asm("sqrt.approx.f32 %0, %1;" : "=f"(r) : "f"(x));
    return r;
}

#define LDSM_X4(r, addr)                                                                  \
    asm volatile("ldmatrix.sync.aligned.m8n8.x4.shared.b16 {%0,%1,%2,%3}, [%4];"          \
                 : "=r"((r)[0]), "=r"((r)[1]), "=r"((r)[2]), "=r"((r)[3]) : "r"(addr))

#define CP_ASYNC16(sa, gp)                                                                \
    asm volatile("cp.async.cg.shared.global [%0], [%1], 16;" :: "r"(sa), "l"(gp) : "memory")
#define CP_COMMIT() asm volatile("cp.async.commit_group;" ::: "memory")
#define CP_WAIT(n)  asm volatile("cp.async.wait_group %0;" :: "n"(n) : "memory")

__device__ __forceinline__ void mma16816(float* c, uint32_t a0, uint32_t a1, uint32_t a2,
                                         uint32_t a3, uint32_t b0, uint32_t b1) {
    asm volatile("mma.sync.aligned.m16n8k16.row.col.f32.f16.f16.f32 "
                 "{%0,%1,%2,%3}, {%4,%5,%6,%7}, {%8,%9}, {%0,%1,%2,%3};"
                 : "+f"(c[0]), "+f"(c[1]), "+f"(c[2]), "+f"(c[3])
                 : "r"(a0), "r"(a1), "r"(a2), "r"(a3), "r"(b0), "r"(b1));
}

// smem: 128x64 jobs, K-chunk 32, row stride 80 B (r*80 mod 128B cycles all 8
// 16B-banks -> conflict-free ldmatrix). Planes: A-hi(128), B-hi(64), B-lo(64).
#define SMA32 80
#define APLANE 10240          // 128*80
#define BPLANE 5120           // 64*80
#define BOFF0  10240          // B-hi offset within chunk
#define CHUNK  20480          // A-hi, B-hi, B-lo
#define OFF_CI 40960          // 128 float2
#define OFF_CJ 41984          // 64 float2
#define SMEM_TOTAL 42496
#define OFF_AVT 0             // 64*132*4 = 33792, reuses buffers after MMA
#define AVT_S 132
#define DOT_SCALE 0.00390625f // 1/256 compensates the x16 feature pre-scale

// ---------- prep: normalize rows, scale x16, split to fp16 hi/lo ----------
__global__ void prep_kernel(const float* __restrict__ fea) {
    int row  = blockIdx.x * 8 + (threadIdx.x >> 5);
    int lane = threadIdx.x & 31;
    float4 v = reinterpret_cast<const float4*>(fea + (size_t)row * ND)[lane];
    float s = v.x * v.x + v.y * v.y + v.z * v.z + v.w * v.w;
    #pragma unroll
    for (int o = 16; o > 0; o >>= 1) s += __shfl_xor_sync(0xffffffffu, s, o);
    float rn = 16.0f / fmaxf(sqrtf(s), 1e-8f);
    float x0 = v.x * rn, x1 = v.y * rn, x2 = v.z * rn, x3 = v.w * rn;
    __half h0 = __float2half_rn(x0), h1 = __float2half_rn(x1);
    __half h2 = __float2half_rn(x2), h3 = __float2half_rn(x3);
    __half l0 = __float2half_rn(x0 - __half2float(h0));
    __half l1 = __float2half_rn(x1 - __half2float(h1));
    __half l2 = __float2half_rn(x2 - __half2float(h2));
    __half l3 = __float2half_rn(x3 - __half2float(h3));
    uint2 hv, lv;
    hv.x = (uint32_t)__half_as_ushort(h0) | ((uint32_t)__half_as_ushort(h1) << 16);
    hv.y = (uint32_t)__half_as_ushort(h2) | ((uint32_t)__half_as_ushort(h3) << 16);
    lv.x = (uint32_t)__half_as_ushort(l0) | ((uint32_t)__half_as_ushort(l1) << 16);
    lv.y = (uint32_t)__half_as_ushort(l2) | ((uint32_t)__half_as_ushort(l3) << 16);
    reinterpret_cast<uint2*>(g_hi)[(size_t)row * 32 + lane] = hv;
    reinterpret_cast<uint2*>(g_lo)[(size_t)row * 32 + lane] = lv;
}

// issue one K32 chunk: A-hi 512 + B-hi 256 + B-lo 256 uint4 = 4/thread
__device__ __forceinline__ void issue_chunk(uint32_t bufBase, int tid, int b,
                                            int iBase, int jBase64, int kc) {
    #pragma unroll
    for (int it = 0; it < 4; it++) {
        int idx = tid + it * 256;
        int row, c8, grow;
        uint32_t soff;
        const uint4* src;
        if (idx < 512) {                   // A-hi
            row = idx >> 2;
            c8 = (idx & 3) * 8;
            grow = iBase + row;
            src = g_hi;
            soff = (uint32_t)(row * SMA32 + c8 * 2);
        } else {                           // B planes
            int e = idx - 512;
            int bplane = e >> 8;           // 0 hi, 1 lo
            int e2 = e & 255;
            row = e2 >> 2;
            c8 = (e2 & 3) * 8;
            grow = jBase64 + row;
            src = bplane ? g_lo : g_hi;
            soff = (uint32_t)(BOFF0 + bplane * BPLANE + row * SMA32 + c8 * 2);
        }
        const uint4* gp = &src[((size_t)(b * NN + grow) * ND + kc * 32 + c8) >> 3];
        CP_ASYNC16(bufBase + soff, gp);
    }
    CP_COMMIT();
}

// ---------- main: 128x64 half-tile jobs, 256 threads, 3 CTAs/SM ----------
__global__ __launch_bounds__(256, 3)
void adj_mma_kernel(const float* __restrict__ coord, float* __restrict__ out) {
    extern __shared__ char sm[];
    const uint32_t smb = smem_u32(sm);
    const int tid  = threadIdx.x;
    const int wid  = tid >> 5;
    const int lane = tid & 31;
    const int wy = wid & 3;           // 0..3, m dim (32 rows each)
    const int wx = wid >> 2;          // 0..1, n dim (32 cols each)

    const int blk = blockIdx.x;
    const int b = blk / 20;
    const int rem = blk % 20;
    const int t = rem >> 1;
    const int jHalf = rem & 1;
    const unsigned char bi_t[10] = {0,0,0,0,1,1,1,2,2,3};
    const unsigned char bj_t[10] = {0,1,2,3,1,2,3,2,3,3};
    const int iBase = bi_t[t] * 128;
    const int jBase = bj_t[t] * 128;
    const int jBase64 = jBase + jHalf * 64;
    const bool diag = (iBase == jBase);

    // prologue: chunks 0,1 in flight
    issue_chunk(smb,         tid, b, iBase, jBase64, 0);
    issue_chunk(smb + CHUNK, tid, b, iBase, jBase64, 1);

    // stage coords while loads stream
    {
        float2* ci2 = reinterpret_cast<float2*>(sm + OFF_CI);
        float2* cj2 = reinterpret_cast<float2*>(sm + OFF_CJ);
        if (tid < 128)
            ci2[tid] = reinterpret_cast<const float2*>(coord)[(size_t)b * NN + iBase + tid];
        else if (tid < 192)
            cj2[tid - 128] = reinterpret_cast<const float2*>(coord)[(size_t)b * NN + jBase64 + (tid - 128)];
    }

    float acc[2][4][4];
    #pragma unroll
    for (int mt = 0; mt < 2; mt++)
        #pragma unroll
        for (int nt = 0; nt < 4; nt++)
            #pragma unroll
            for (int q = 0; q < 4; q++) acc[mt][nt][q] = 0.0f;

    const uint32_t aOff = (uint32_t)((wy * 32 + lane) * SMA32);
    const uint32_t bOff = (uint32_t)(BOFF0 + (wx * 32 + lane) * SMA32);

    #pragma unroll
    for (int kc = 0; kc < 4; kc++) {
        if (kc < 3) CP_WAIT(1); else CP_WAIT(0);
        __syncthreads();

        const uint32_t buf = smb + (uint32_t)((kc & 1) * CHUNK);
        const uint32_t aH = buf + aOff;
        const uint32_t bH = buf + bOff;
        const uint32_t bL = bH + BPLANE;

        #pragma unroll
        for (int ks = 0; ks < 2; ks++) {
            const uint32_t co = (uint32_t)(ks * 32);
            uint32_t ah1[4], ah2[4], bh1[4], bh2[4];
            LDSM_X4(ah1, aH + co);
            LDSM_X4(ah2, aH + co + 16);
            LDSM_X4(bh1, bH + co);
            LDSM_X4(bh2, bH + co + 16);
            #pragma unroll
            for (int mt = 0; mt < 2; mt++)
                #pragma unroll
                for (int nt = 0; nt < 4; nt++)
                    mma16816(acc[mt][nt], ah1[mt*2], ah1[mt*2+1], ah2[mt*2], ah2[mt*2+1],
                             bh1[nt], bh2[nt]);
            {
                uint32_t bl1[4], bl2[4];
                LDSM_X4(bl1, bL + co);
                LDSM_X4(bl2, bL + co + 16);
                #pragma unroll
                for (int mt = 0; mt < 2; mt++)
                    #pragma unroll
                    for (int nt = 0; nt < 4; nt++)
                        mma16816(acc[mt][nt], ah1[mt*2], ah1[mt*2+1], ah2[mt*2], ah2[mt*2+1],
                                 bl1[nt], bl2[nt]);
            }
        }

        __syncthreads();
        if (kc < 2) issue_chunk(buf, tid, b, iBase, jBase64, kc + 2);
    }

    // epilogue: direct stores from fragments + transposed staging for mirror
    {
        const float2* ci2 = reinterpret_cast<const float2*>(sm + OFF_CI);
        const float2* cj2 = reinterpret_cast<const float2*>(sm + OFF_CJ);
        float* avt = reinterpret_cast<float*>(sm + OFF_AVT);
        float* outA = out;
        float* outS = out + (size_t)NB * NN * NN;
        const size_t base = (size_t)b * NN * NN;
        const int g = lane >> 2, q = lane & 3;

        #pragma unroll
        for (int mt = 0; mt < 2; mt++) {
            #pragma unroll
            for (int nt = 0; nt < 4; nt++) {
                const float* c = acc[mt][nt];
                const int lj = wx * 32 + nt * 8 + q * 2;       // 0..63
                const float2 cj0 = cj2[lj], cj1 = cj2[lj + 1];
                #pragma unroll
                for (int h = 0; h < 2; h++) {
                    const int li = wy * 32 + mt * 16 + g + h * 8;   // 0..127
                    const float2 ci = ci2[li];
                    float dx0 = ci.x - cj0.x, dy0 = ci.y - cj0.y;
                    float dx1 = ci.x - cj1.x, dy1 = ci.y - cj1.y;
                    float d20 = dx0 * dx0 + dy0 * dy0;
                    float d21 = dx1 * dx1 + dy1 * dy1;
                    bool s0 = diag && (li == jHalf * 64 + lj);
                    bool s1 = diag && (li == jHalf * 64 + lj + 1);
                    float e0 = __expf(-fsqrt_approx(d20)) * DOT_SCALE;
                    float e1 = __expf(-fsqrt_approx(d21)) * DOT_SCALE;
                    float av0 = s0 ? 0.0f : c[h * 2 + 0] * e0;
                    float av1 = s1 ? 0.0f : c[h * 2 + 1] * e1;
                    float sv0 = (!s0 && d20 < 1.0f) ? 1.0f : 0.0f;
                    float sv1 = (!s1 && d21 < 1.0f) ? 1.0f : 0.0f;
                    size_t ro = base + (size_t)(iBase + li) * NN + jBase64 + lj;
                    *reinterpret_cast<float2*>(outA + ro) = make_float2(av0, av1);
                    *reinterpret_cast<float2*>(outS + ro) = make_float2(sv0, sv1);
                    if (!diag) {
                        avt[(size_t)lj * AVT_S + li]       = av0;
                        avt[(size_t)(lj + 1) * AVT_S + li] = av1;
                    }
                }
            }
        }
    }

    // mirror pass: 64 rows (j) x 128 cols (i)
    if (!diag) {
        __syncthreads();
        const float* avt = reinterpret_cast<const float*>(sm + OFF_AVT);
        const float2* cj2 = reinterpret_cast<const float2*>(sm + OFF_CJ);
        const float4* ci4 = reinterpret_cast<const float4*>(sm + OFF_CI);
        float* outA = out;
        float* outS = out + (size_t)NB * NN * NN;
        const size_t base = (size_t)b * NN * NN;

        #pragma unroll
        for (int it = 0; it < 8; it++) {
            const int r = wid * 8 + it;     // local j row, 0..63
            float4 av4 = *reinterpret_cast<const float4*>(avt + (size_t)r * AVT_S + lane * 4);
            float2 cj = cj2[r];
            float4 p0 = ci4[lane * 2], p1 = ci4[lane * 2 + 1];
            float d0x = cj.x - p0.x, d0y = cj.y - p0.y;
            float d1x = cj.x - p0.z, d1y = cj.y - p0.w;
            float d2x = cj.x - p1.x, d2y = cj.y - p1.y;
            float d3x = cj.x - p1.z, d3y = cj.y - p1.w;
            float4 sv4;
            sv4.x = (d0x * d0x + d0y * d0y < 1.0f) ? 1.0f : 0.0f;
            sv4.y = (d1x * d1x + d1y * d1y < 1.0f) ? 1.0f : 0.0f;
            sv4.z = (d2x * d2x + d2y * d2y < 1.0f) ? 1.0f : 0.0f;
            sv4.w = (d3x * d3x + d3y * d3y < 1.0f) ? 1.0f : 0.0f;
            size_t ro = base + (size_t)(jBase64 + r) * NN + iBase + lane * 4;
            *reinterpret_cast<float4*>(outA + ro) = av4;
            *reinterpret_cast<float4*>(outS + ro) = sv4;
        }
    }
}

extern "C" void kernel_launch(void* const* d_in, const int* in_sizes, int n_in,
                              void* d_out, int out_size) {
    (void)in_sizes; (void)n_in; (void)out_size;
    const float* fea   = (const float*)d_in[0];
    const float* coord = (const float*)d_in[1];
    float* out = (float*)d_out;

    prep_kernel<<<NB * NN / 8, 256>>>(fea);

    cudaFuncSetAttribute(adj_mma_kernel, cudaFuncAttributeMaxDynamicSharedMemorySize, SMEM_TOTAL);
    adj_mma_kernel<<<NB * 20, 256, SMEM_TOTAL>>>(coord, out);
}

// round 13
// speedup vs baseline: 1.4257x; 1.1415x over previous
#include <cuda_runtime.h>
#include <cuda_fp16.h>
#include <cstdint>

#define NB 64
#define NN 512
#define ND 128

// pre-normalized features (scaled x16), fp16
__device__ uint4 g_hi[(NB * NN * ND * 2) / 16];

__device__ __forceinline__ uint32_t smem_u32(const void* p) {
    uint32_t a;
    asm("{ .reg .u64 t; cvta.to.shared.u64 t, %1; cvt.u32.u64 %0, t; }" : "=r"(a) : "l"(p));
    return a;
}
__device__ __forceinline__ float fsqrt_approx(float x) {
    float r;
    asm("sqrt.approx.f32 %0, %1;" : "=f"(r) : "f"(x));
    return r;
}

#define LDSM_X4(r, addr)                                                                  \
    asm volatile("ldmatrix.sync.aligned.m8n8.x4.shared.b16 {%0,%1,%2,%3}, [%4];"          \
                 : "=r"((r)[0]), "=r"((r)[1]), "=r"((r)[2]), "=r"((r)[3]) : "r"(addr))

#define CP_ASYNC16(sa, gp)                                                                \
    asm volatile("cp.async.cg.shared.global [%0], [%1], 16;" :: "r"(sa), "l"(gp) : "memory")
#define CP_COMMIT() asm volatile("cp.async.commit_group;" ::: "memory")
#define CP_WAIT(n)  asm volatile("cp.async.wait_group %0;" :: "n"(n) : "memory")

__device__ __forceinline__ void mma16816(float* c, uint32_t a0, uint32_t a1, uint32_t a2,
                                         uint32_t a3, uint32_t b0, uint32_t b1) {
    asm volatile("mma.sync.aligned.m16n8k16.row.col.f32.f16.f16.f32 "
                 "{%0,%1,%2,%3}, {%4,%5,%6,%7}, {%8,%9}, {%0,%1,%2,%3};"
                 : "+f"(c[0]), "+f"(c[1]), "+f"(c[2]), "+f"(c[3])
                 : "r"(a0), "r"(a1), "r"(a2), "r"(a3), "r"(b0), "r"(b1));
}

// smem: 128x64 jobs, K-chunk 32, row stride 80 B (r*80 mod 128B cycles all 8
// 16B-banks -> conflict-free ldmatrix). Planes: A(128 rows), B(64 rows).
#define SMA32 80
#define APLANE 10240          // 128*80
#define BPLANE 5120           // 64*80
#define BOFF0  10240          // B offset within chunk
#define CHUNK  15360          // A + B
#define OFF_AVT 0             // 64*132*4 = 33792, reuses buffers after MMA
#define AVT_S 132
#define OFF_CI 33792          // 128 float2 (past avt region)
#define OFF_CJ 34816          // 64 float2
#define SMEM_TOTAL 35328
#define DOT_SCALE 0.00390625f // 1/256 compensates the x16 feature pre-scale

// ---------- prep: normalize rows, scale x16, to fp16 ----------
__global__ void prep_kernel(const float* __restrict__ fea) {
    int row  = blockIdx.x * 8 + (threadIdx.x >> 5);
    int lane = threadIdx.x & 31;
    float4 v = reinterpret_cast<const float4*>(fea + (size_t)row * ND)[lane];
    float s = v.x * v.x + v.y * v.y + v.z * v.z + v.w * v.w;
    #pragma unroll
    for (int o = 16; o > 0; o >>= 1) s += __shfl_xor_sync(0xffffffffu, s, o);
    float rn = 16.0f / fmaxf(sqrtf(s), 1e-8f);
    __half h0 = __float2half_rn(v.x * rn), h1 = __float2half_rn(v.y * rn);
    __half h2 = __float2half_rn(v.z * rn), h3 = __float2half_rn(v.w * rn);
    uint2 hv;
    hv.x = (uint32_t)__half_as_ushort(h0) | ((uint32_t)__half_as_ushort(h1) << 16);
    hv.y = (uint32_t)__half_as_ushort(h2) | ((uint32_t)__half_as_ushort(h3) << 16);
    reinterpret_cast<uint2*>(g_hi)[(size_t)row * 32 + lane] = hv;
}

// issue one K32 chunk: A 512 + B 256 uint4 = 3/thread
__device__ __forceinline__ void issue_chunk(uint32_t bufBase, int tid, int b,
                                            int iBase, int jBase64, int kc) {
    #pragma unroll
    for (int it = 0; it < 3; it++) {
        int idx = tid + it * 256;
        int row, c8, grow;
        uint32_t soff;
        if (idx < 512) {                   // A rows
            row = idx >> 2;
            c8 = (idx & 3) * 8;
            grow = iBase + row;
            soff = (uint32_t)(row * SMA32 + c8 * 2);
        } else {                           // B rows
            int e = idx - 512;
            row = e >> 2;
            c8 = (e & 3) * 8;
            grow = jBase64 + row;
            soff = (uint32_t)(BOFF0 + row * SMA32 + c8 * 2);
        }
        const uint4* gp = &g_hi[((size_t)(b * NN + grow) * ND + kc * 32 + c8) >> 3];
        CP_ASYNC16(bufBase + soff, gp);
    }
    CP_COMMIT();
}

// ---------- main: 128x64 half-tile jobs, 256 threads, 3 CTAs/SM ----------
__global__ __launch_bounds__(256, 3)
void adj_mma_kernel(const float* __restrict__ coord, float* __restrict__ out) {
    extern __shared__ char sm[];
    const uint32_t smb = smem_u32(sm);
    const int tid  = threadIdx.x;
    const int wid  = tid >> 5;
    const int lane = tid & 31;
    const int wy = wid & 3;           // 0..3, m dim (32 rows each)
    const int wx = wid >> 2;          // 0..1, n dim (32 cols each)

    const int blk = blockIdx.x;
    const int b = blk / 20;
    const int rem = blk % 20;
    const int t = rem >> 1;
    const int jHalf = rem & 1;
    const unsigned char bi_t[10] = {0,0,0,0,1,1,1,2,2,3};
    const unsigned char bj_t[10] = {0,1,2,3,1,2,3,2,3,3};
    const int iBase = bi_t[t] * 128;
    const int jBase = bj_t[t] * 128;
    const int jBase64 = jBase + jHalf * 64;
    const bool diag = (iBase == jBase);

    // prologue: chunks 0,1 in flight
    issue_chunk(smb,         tid, b, iBase, jBase64, 0);
    issue_chunk(smb + CHUNK, tid, b, iBase, jBase64, 1);

    // stage coords while loads stream
    {
        float2* ci2 = reinterpret_cast<float2*>(sm + OFF_CI);
        float2* cj2 = reinterpret_cast<float2*>(sm + OFF_CJ);
        if (tid < 128)
            ci2[tid] = reinterpret_cast<const float2*>(coord)[(size_t)b * NN + iBase + tid];
        else if (tid < 192)
            cj2[tid - 128] = reinterpret_cast<const float2*>(coord)[(size_t)b * NN + jBase64 + (tid - 128)];
    }

    float acc[2][4][4];
    #pragma unroll
    for (int mt = 0; mt < 2; mt++)
        #pragma unroll
        for (int nt = 0; nt < 4; nt++)
            #pragma unroll
            for (int q = 0; q < 4; q++) acc[mt][nt][q] = 0.0f;

    const uint32_t aOff = (uint32_t)((wy * 32 + lane) * SMA32);
    const uint32_t bOff = (uint32_t)(BOFF0 + (wx * 32 + lane) * SMA32);

    #pragma unroll
    for (int kc = 0; kc < 4; kc++) {
        if (kc < 3) CP_WAIT(1); else CP_WAIT(0);
        __syncthreads();

        const uint32_t buf = smb + (uint32_t)((kc & 1) * CHUNK);
        const uint32_t aH = buf + aOff;
        const uint32_t bH = buf + bOff;

        #pragma unroll
        for (int ks = 0; ks < 2; ks++) {
            const uint32_t co = (uint32_t)(ks * 32);
            uint32_t ah1[4], ah2[4], bh1[4], bh2[4];
            LDSM_X4(ah1, aH + co);
            LDSM_X4(ah2, aH + co + 16);
            LDSM_X4(bh1, bH + co);
            LDSM_X4(bh2, bH + co + 16);
            #pragma unroll
            for (int mt = 0; mt < 2; mt++)
                #pragma unroll
                for (int nt = 0; nt < 4; nt++)
                    mma16816(acc[mt][nt], ah1[mt*2], ah1[mt*2+1], ah2[mt*2], ah2[mt*2+1],
                             bh1[nt], bh2[nt]);
        }

        __syncthreads();
        if (kc < 2) issue_chunk(buf, tid, b, iBase, jBase64, kc + 2);
    }

    // epilogue: direct stores from fragments + transposed staging for mirror
    {
        const float2* ci2 = reinterpret_cast<const float2*>(sm + OFF_CI);
        const float2* cj2 = reinterpret_cast<const float2*>(sm + OFF_CJ);
        float* avt = reinterpret_cast<float*>(sm + OFF_AVT);
        float* outA = out;
        float* outS = out + (size_t)NB * NN * NN;
        const size_t base = (size_t)b * NN * NN;
        const int g = lane >> 2, q = lane & 3;

        #pragma unroll
        for (int mt = 0; mt < 2; mt++) {
            #pragma unroll
            for (int nt = 0; nt < 4; nt++) {
                const float* c = acc[mt][nt];
                const int lj = wx * 32 + nt * 8 + q * 2;       // 0..63
                const float2 cj0 = cj2[lj], cj1 = cj2[lj + 1];
                #pragma unroll
                for (int h = 0; h < 2; h++) {
                    const int li = wy * 32 + mt * 16 + g + h * 8;   // 0..127
                    const float2 ci = ci2[li];
                    float dx0 = ci.x - cj0.x, dy0 = ci.y - cj0.y;
                    float dx1 = ci.x - cj1.x, dy1 = ci.y - cj1.y;
                    float d20 = dx0 * dx0 + dy0 * dy0;
                    float d21 = dx1 * dx1 + dy1 * dy1;
                    bool s0 = diag && (li == jHalf * 64 + lj);
                    bool s1 = diag && (li == jHalf * 64 + lj + 1);
                    float e0 = __expf(-fsqrt_approx(d20)) * DOT_SCALE;
                    float e1 = __expf(-fsqrt_approx(d21)) * DOT_SCALE;
                    float av0 = s0 ? 0.0f : c[h * 2 + 0] * e0;
                    float av1 = s1 ? 0.0f : c[h * 2 + 1] * e1;
                    float sv0 = (!s0 && d20 < 1.0f) ? 1.0f : 0.0f;
                    float sv1 = (!s1 && d21 < 1.0f) ? 1.0f : 0.0f;
                    size_t ro = base + (size_t)(iBase + li) * NN + jBase64 + lj;
                    *reinterpret_cast<float2*>(outA + ro) = make_float2(av0, av1);
                    *reinterpret_cast<float2*>(outS + ro) = make_float2(sv0, sv1);
                    if (!diag) {
                        avt[(size_t)lj * AVT_S + li]       = av0;
                        avt[(size_t)(lj + 1) * AVT_S + li] = av1;
                    }
                }
            }
        }
    }

    // mirror pass: 64 rows (j) x 128 cols (i)
    if (!diag) {
        __syncthreads();
        const float* avt = reinterpret_cast<const float*>(sm + OFF_AVT);
        const float2* cj2 = reinterpret_cast<const float2*>(sm + OFF_CJ);
        const float4* ci4 = reinterpret_cast<const float4*>(sm + OFF_CI);
        float* outA = out;
        float* outS = out + (size_t)NB * NN * NN;
        const size_t base = (size_t)b * NN * NN;

        #pragma unroll
        for (int it = 0; it < 8; it++) {
            const int r = wid * 8 + it;     // local j row, 0..63
            float4 av4 = *reinterpret_cast<const float4*>(avt + (size_t)r * AVT_S + lane * 4);
            float2 cj = cj2[r];
            float4 p0 = ci4[lane * 2], p1 = ci4[lane * 2 + 1];
            float d0x = cj.x - p0.x, d0y = cj.y - p0.y;
            float d1x = cj.x - p0.z, d1y = cj.y - p0.w;
            float d2x = cj.x - p1.x, d2y = cj.y - p1.y;
            float d3x = cj.x - p1.z, d3y = cj.y - p1.w;
            float4 sv4;
            sv4.x = (d0x * d0x + d0y * d0y < 1.0f) ? 1.0f : 0.0f;
            sv4.y = (d1x * d1x + d1y * d1y < 1.0f) ? 1.0f : 0.0f;
            sv4.z = (d2x * d2x + d2y * d2y < 1.0f) ? 1.0f : 0.0f;
            sv4.w = (d3x * d3x + d3y * d3y < 1.0f) ? 1.0f : 0.0f;
            size_t ro = base + (size_t)(jBase64 + r) * NN + iBase + lane * 4;
            *reinterpret_cast<float4*>(outA + ro) = av4;
            *reinterpret_cast<float4*>(outS + ro) = sv4;
        }
    }
}

extern "C" void kernel_launch(void* const* d_in, const int* in_sizes, int n_in,
                              void* d_out, int out_size) {
    (void)in_sizes; (void)n_in; (void)out_size;
    const float* fea   = (const float*)d_in[0];
    const float* coord = (const float*)d_in[1];
    float* out = (float*)d_out;

    prep_kernel<<<NB * NN / 8, 256>>>(fea);

    cudaFuncSetAttribute(adj_mma_kernel, cudaFuncAttributeMaxDynamicSharedMemorySize, SMEM_TOTAL);
    adj_mma_kernel<<<NB * 20, 256, SMEM_TOTAL>>>(coord, out);
}

// round 14
// speedup vs baseline: 1.4789x; 1.0374x over previous
#include <cuda_runtime.h>
#include <cuda_fp16.h>
#include <cstdint>

#define NB 64
#define NN 512
#define ND 128

// pre-normalized features (scaled x16), fp16
__device__ uint4 g_hi[(NB * NN * ND * 2) / 16];

__device__ __forceinline__ uint32_t smem_u32(const void* p) {
    uint32_t a;
    asm("{ .reg .u64 t; cvta.to.shared.u64 t, %1; cvt.u32.u64 %0, t; }" : "=r"(a) : "l"(p));
    return a;
}
__device__ __forceinline__ float fsqrt_approx(float x) {
    float r;
    asm("sqrt.approx.f32 %0, %1;" : "=f"(r) : "f"(x));
    return r;
}

#define LDSM_X4(r, addr)                                                                  \
    asm volatile("ldmatrix.sync.aligned.m8n8.x4.shared.b16 {%0,%1,%2,%3}, [%4];"          \
                 : "=r"((r)[0]), "=r"((r)[1]), "=r"((r)[2]), "=r"((r)[3]) : "r"(addr))

#define CP_ASYNC16(sa, gp)                                                                \
    asm volatile("cp.async.cg.shared.global [%0], [%1], 16;" :: "r"(sa), "l"(gp) : "memory")
#define CP_COMMIT() asm volatile("cp.async.commit_group;" ::: "memory")
#define CP_WAIT(n)  asm volatile("cp.async.wait_group %0;" :: "n"(n) : "memory")

__device__ __forceinline__ void mma16816(float* c, uint32_t a0, uint32_t a1, uint32_t a2,
                                         uint32_t a3, uint32_t b0, uint32_t b1) {
    asm volatile("mma.sync.aligned.m16n8k16.row.col.f32.f16.f16.f32 "
                 "{%0,%1,%2,%3}, {%4,%5,%6,%7}, {%8,%9}, {%0,%1,%2,%3};"
                 : "+f"(c[0]), "+f"(c[1]), "+f"(c[2]), "+f"(c[3])
                 : "r"(a0), "r"(a1), "r"(a2), "r"(a3), "r"(b0), "r"(b1));
}

// ---- smem layout (bytes) ----
// coords first (live whole kernel), then mainloop buffers, then (overlapping,
// after the last mainloop sync) the av staging planes.
#define OFF_CI 0              // 128 float2 = 1024
#define OFF_CJ 1024           // 64 float2 = 512
#define OFF_BUF 1536
#define SMA32 80              // operand row stride (conflict-free ldmatrix)
#define APLANE 10240          // 128*80
#define BOFF0  10240          // B plane offset within chunk
#define CHUNK  15360          // A(128 rows) + B(64 rows)
#define OFF_AVS 1536          // 128 x 72 floats = 36864 (overlaps buffers)
#define AVS_S 72
#define OFF_AVT 38400         // 64 x 132 floats = 33792
#define AVT_S 132
#define SMEM_TOTAL 72192
#define DOT_SCALE 0.00390625f // 1/256 compensates the x16 feature pre-scale

// ---------- prep: normalize rows, scale x16, to fp16 ----------
__global__ void prep_kernel(const float* __restrict__ fea) {
    int row  = blockIdx.x * 8 + (threadIdx.x >> 5);
    int lane = threadIdx.x & 31;
    float4 v = reinterpret_cast<const float4*>(fea + (size_t)row * ND)[lane];
    float s = v.x * v.x + v.y * v.y + v.z * v.z + v.w * v.w;
    #pragma unroll
    for (int o = 16; o > 0; o >>= 1) s += __shfl_xor_sync(0xffffffffu, s, o);
    float rn = 16.0f / fmaxf(sqrtf(s), 1e-8f);
    __half h0 = __float2half_rn(v.x * rn), h1 = __float2half_rn(v.y * rn);
    __half h2 = __float2half_rn(v.z * rn), h3 = __float2half_rn(v.w * rn);
    uint2 hv;
    hv.x = (uint32_t)__half_as_ushort(h0) | ((uint32_t)__half_as_ushort(h1) << 16);
    hv.y = (uint32_t)__half_as_ushort(h2) | ((uint32_t)__half_as_ushort(h3) << 16);
    reinterpret_cast<uint2*>(g_hi)[(size_t)row * 32 + lane] = hv;
}

// issue one K32 chunk: A 512 + B 256 uint4 = 3/thread
__device__ __forceinline__ void issue_chunk(uint32_t bufBase, int tid, int b,
                                            int iBase, int jBase64, int kc) {
    #pragma unroll
    for (int it = 0; it < 3; it++) {
        int idx = tid + it * 256;
        int row, c8, grow;
        uint32_t soff;
        if (idx < 512) {                   // A rows
            row = idx >> 2;
            c8 = (idx & 3) * 8;
            grow = iBase + row;
            soff = (uint32_t)(row * SMA32 + c8 * 2);
        } else {                           // B rows
            int e = idx - 512;
            row = e >> 2;
            c8 = (e & 3) * 8;
            grow = jBase64 + row;
            soff = (uint32_t)(BOFF0 + row * SMA32 + c8 * 2);
        }
        const uint4* gp = &g_hi[((size_t)(b * NN + grow) * ND + kc * 32 + c8) >> 3];
        CP_ASYNC16(bufBase + soff, gp);
    }
    CP_COMMIT();
}

// ---------- main: 128x64 half-tile jobs, 256 threads, 3 CTAs/SM ----------
__global__ __launch_bounds__(256, 3)
void adj_mma_kernel(const float* __restrict__ coord, float* __restrict__ out) {
    extern __shared__ char sm[];
    const uint32_t smb = smem_u32(sm);
    const int tid  = threadIdx.x;
    const int wid  = tid >> 5;
    const int lane = tid & 31;
    const int wy = wid & 3;           // 0..3, m dim (32 rows each)
    const int wx = wid >> 2;          // 0..1, n dim (32 cols each)

    const int blk = blockIdx.x;
    const int b = blk / 20;
    const int rem = blk % 20;
    const int t = rem >> 1;
    const int jHalf = rem & 1;
    const unsigned char bi_t[10] = {0,0,0,0,1,1,1,2,2,3};
    const unsigned char bj_t[10] = {0,1,2,3,1,2,3,2,3,3};
    const int iBase = bi_t[t] * 128;
    const int jBase = bj_t[t] * 128;
    const int jBase64 = jBase + jHalf * 64;
    const bool diag = (iBase == jBase);

    // prologue: chunks 0,1 in flight
    issue_chunk(smb + OFF_BUF,         tid, b, iBase, jBase64, 0);
    issue_chunk(smb + OFF_BUF + CHUNK, tid, b, iBase, jBase64, 1);

    // stage coords while loads stream
    {
        float2* ci2 = reinterpret_cast<float2*>(sm + OFF_CI);
        float2* cj2 = reinterpret_cast<float2*>(sm + OFF_CJ);
        if (tid < 128)
            ci2[tid] = reinterpret_cast<const float2*>(coord)[(size_t)b * NN + iBase + tid];
        else if (tid < 192)
            cj2[tid - 128] = reinterpret_cast<const float2*>(coord)[(size_t)b * NN + jBase64 + (tid - 128)];
    }

    float acc[2][4][4];
    #pragma unroll
    for (int mt = 0; mt < 2; mt++)
        #pragma unroll
        for (int nt = 0; nt < 4; nt++)
            #pragma unroll
            for (int q = 0; q < 4; q++) acc[mt][nt][q] = 0.0f;

    const uint32_t aOff = (uint32_t)(OFF_BUF + (wy * 32 + lane) * SMA32);
    const uint32_t bOff = (uint32_t)(OFF_BUF + BOFF0 + (wx * 32 + lane) * SMA32);

    #pragma unroll
    for (int kc = 0; kc < 4; kc++) {
        if (kc < 3) CP_WAIT(1); else CP_WAIT(0);
        __syncthreads();

        const uint32_t bsel = (uint32_t)((kc & 1) * CHUNK);
        const uint32_t aH = smb + aOff + bsel;
        const uint32_t bH = smb + bOff + bsel;

        #pragma unroll
        for (int ks = 0; ks < 2; ks++) {
            const uint32_t co = (uint32_t)(ks * 32);
            uint32_t ah1[4], ah2[4], bh1[4], bh2[4];
            LDSM_X4(ah1, aH + co);
            LDSM_X4(ah2, aH + co + 16);
            LDSM_X4(bh1, bH + co);
            LDSM_X4(bh2, bH + co + 16);
            #pragma unroll
            for (int mt = 0; mt < 2; mt++)
                #pragma unroll
                for (int nt = 0; nt < 4; nt++)
                    mma16816(acc[mt][nt], ah1[mt*2], ah1[mt*2+1], ah2[mt*2], ah2[mt*2+1],
                             bh1[nt], bh2[nt]);
        }

        __syncthreads();
        if (kc < 2) issue_chunk(smb + OFF_BUF + bsel, tid, b, iBase, jBase64, kc + 2);
    }

    // stage av (row-major + transposed) to smem; no gmem stores here
    {
        const float2* ci2 = reinterpret_cast<const float2*>(sm + OFF_CI);
        const float2* cj2 = reinterpret_cast<const float2*>(sm + OFF_CJ);
        float* avs = reinterpret_cast<float*>(sm + OFF_AVS);
        float* avt = reinterpret_cast<float*>(sm + OFF_AVT);
        const int g = lane >> 2, q = lane & 3;

        #pragma unroll
        for (int mt = 0; mt < 2; mt++) {
            #pragma unroll
            for (int nt = 0; nt < 4; nt++) {
                const float* c = acc[mt][nt];
                const int lj = wx * 32 + nt * 8 + q * 2;       // 0..63
                const float2 cj0 = cj2[lj], cj1 = cj2[lj + 1];
                #pragma unroll
                for (int h = 0; h < 2; h++) {
                    const int li = wy * 32 + mt * 16 + g + h * 8;   // 0..127
                    const float2 ci = ci2[li];
                    float dx0 = ci.x - cj0.x, dy0 = ci.y - cj0.y;
                    float dx1 = ci.x - cj1.x, dy1 = ci.y - cj1.y;
                    float d20 = dx0 * dx0 + dy0 * dy0;
                    float d21 = dx1 * dx1 + dy1 * dy1;
                    bool s0 = diag && (li == jHalf * 64 + lj);
                    bool s1 = diag && (li == jHalf * 64 + lj + 1);
                    float av0 = s0 ? 0.0f : c[h * 2 + 0] * (__expf(-fsqrt_approx(d20)) * DOT_SCALE);
                    float av1 = s1 ? 0.0f : c[h * 2 + 1] * (__expf(-fsqrt_approx(d21)) * DOT_SCALE);
                    *reinterpret_cast<float2*>(avs + (size_t)li * AVS_S + lj) = make_float2(av0, av1);
                    if (!diag) {
                        avt[(size_t)lj * AVT_S + li]       = av0;
                        avt[(size_t)(lj + 1) * AVT_S + li] = av1;
                    }
                }
            }
        }
    }
    __syncthreads();

    // coalesced write pass: av from smem, sv recomputed from coords
    {
        const float* avs = reinterpret_cast<const float*>(sm + OFF_AVS);
        const float* avt = reinterpret_cast<const float*>(sm + OFF_AVT);
        const float2* ci2 = reinterpret_cast<const float2*>(sm + OFF_CI);
        const float2* cj2 = reinterpret_cast<const float2*>(sm + OFF_CJ);
        const float4* ci4 = reinterpret_cast<const float4*>(sm + OFF_CI);
        const float4* cj4 = reinterpret_cast<const float4*>(sm + OFF_CJ);
        float* outA = out;
        float* outS = out + (size_t)NB * NN * NN;
        const size_t base = (size_t)b * NN * NN;

        // direct: 128 rows x 64 cols
        #pragma unroll
        for (int it = 0; it < 8; it++) {
            int idx = tid + it * 256;
            int row = idx >> 4;            // 0..127
            int c4 = (idx & 15) * 4;       // 0..60
            float4 av4 = *reinterpret_cast<const float4*>(avs + (size_t)row * AVS_S + c4);
            float2 ci = ci2[row];
            float4 p0 = cj4[c4 >> 1], p1 = cj4[(c4 >> 1) + 1];
            float d0x = ci.x - p0.x, d0y = ci.y - p0.y;
            float d1x = ci.x - p0.z, d1y = ci.y - p0.w;
            float d2x = ci.x - p1.x, d2y = ci.y - p1.y;
            float d3x = ci.x - p1.z, d3y = ci.y - p1.w;
            int dr = row - jHalf * 64 - c4;      // diag when dr == k
            float4 sv4;
            sv4.x = (d0x * d0x + d0y * d0y < 1.0f && !(diag && dr == 0)) ? 1.0f : 0.0f;
            sv4.y = (d1x * d1x + d1y * d1y < 1.0f && !(diag && dr == 1)) ? 1.0f : 0.0f;
            sv4.z = (d2x * d2x + d2y * d2y < 1.0f && !(diag && dr == 2)) ? 1.0f : 0.0f;
            sv4.w = (d3x * d3x + d3y * d3y < 1.0f && !(diag && dr == 3)) ? 1.0f : 0.0f;
            size_t ro = base + (size_t)(iBase + row) * NN + jBase64 + c4;
            *reinterpret_cast<float4*>(outA + ro) = av4;
            *reinterpret_cast<float4*>(outS + ro) = sv4;
        }

        // mirror: 64 rows x 128 cols
        if (!diag) {
            #pragma unroll
            for (int it = 0; it < 8; it++) {
                int idx = tid + it * 256;
                int row = idx >> 5;        // 0..63
                int c4 = (idx & 31) * 4;   // 0..124
                float4 av4 = *reinterpret_cast<const float4*>(avt + (size_t)row * AVT_S + c4);
                float2 cj = cj2[row];
                float4 p0 = ci4[c4 >> 1], p1 = ci4[(c4 >> 1) + 1];
                float d0x = cj.x - p0.x, d0y = cj.y - p0.y;
                float d1x = cj.x - p0.z, d1y = cj.y - p0.w;
                float d2x = cj.x - p1.x, d2y = cj.y - p1.y;
                float d3x = cj.x - p1.z, d3y = cj.y - p1.w;
                float4 sv4;
                sv4.x = (d0x * d0x + d0y * d0y < 1.0f) ? 1.0f : 0.0f;
                sv4.y = (d1x * d1x + d1y * d1y < 1.0f) ? 1.0f : 0.0f;
                sv4.z = (d2x * d2x + d2y * d2y < 1.0f) ? 1.0f : 0.0f;
                sv4.w = (d3x * d3x + d3y * d3y < 1.0f) ? 1.0f : 0.0f;
                size_t ro = base + (size_t)(jBase64 + row) * NN + iBase + c4;
                *reinterpret_cast<float4*>(outA + ro) = av4;
                *reinterpret_cast<float4*>(outS + ro) = sv4;
            }
        }
    }
}

extern "C" void kernel_launch(void* const* d_in, const int* in_sizes, int n_in,
                              void* d_out, int out_size) {
    (void)in_sizes; (void)n_in; (void)out_size;
    const float* fea   = (const float*)d_in[0];
    const float* coord = (const float*)d_in[1];
    float* out = (float*)d_out;

    prep_kernel<<<NB * NN / 8, 256>>>(fea);

    cudaFuncSetAttribute(adj_mma_kernel, cudaFuncAttributeMaxDynamicSharedMemorySize, SMEM_TOTAL);
    adj_mma_kernel<<<NB * 20, 256, SMEM_TOTAL>>>(coord, out);
}